// round 14
// baseline (speedup 1.0000x reference)
#include <cuda_runtime.h>
#include <mma.h>
#include <cstdint>

using namespace nvcuda;

#define MTOK  8192
#define D_    768
#define NCODE 16384
#define THRv  100.0f

#define BM 128
#define BN 128
#define BK 64
#define NSPLIT 16
#define NCHUNK (NCODE / NSPLIT)       // 1024
#define NTILES (NCHUNK / BN)          // 8
#define NKSTEP (D_ / BK)              // 12
#define SROWB  80                     // int8 smem row pitch (64 data + 16 pad bytes)
#define NCAND  (NSPLIT * 4)           // 64 slots: one per (split, column-quarter)

#define QSCALE 25.4f
#define QNEG2  (-2.0f / (QSCALE * QSCALE))

// Scratch (static device memory — allocations are forbidden).
// Referenced ONLY from device code by symbol.
__device__ float g_c2[NCODE];
__device__ float g_x2[MTOK];
__device__ unsigned long long g_cand[MTOK * NCAND];
__device__ __align__(16) signed char g_xq[MTOK * D_];
__device__ __align__(16) signed char g_cq[NCODE * D_];

// ---------------------------------------------------------------------------
__device__ __forceinline__ unsigned pack4(float4 v) {
    int a = max(-127, min(127, __float2int_rn(v.x * QSCALE)));
    int b = max(-127, min(127, __float2int_rn(v.y * QSCALE)));
    int c = max(-127, min(127, __float2int_rn(v.z * QSCALE)));
    int d = max(-127, min(127, __float2int_rn(v.w * QSCALE)));
    return (unsigned)(a & 0xff) | ((unsigned)(b & 0xff) << 8) |
           ((unsigned)(c & 0xff) << 16) | ((unsigned)(d & 0xff) << 24);
}

// fp32 -> int8 staging (16 elems/thread), writing __device__ arrays BY SYMBOL.
__global__ void cvt_x_kernel(const float* __restrict__ in) {
    int i = blockIdx.x * blockDim.x + threadIdx.x;
    if (i >= MTOK * D_ / 16) return;
    const float4* p = (const float4*)in + 4 * (size_t)i;
    uint4 r;
    r.x = pack4(p[0]); r.y = pack4(p[1]); r.z = pack4(p[2]); r.w = pack4(p[3]);
    ((uint4*)g_xq)[i] = r;
}

__global__ void cvt_c_kernel(const float* __restrict__ in) {
    int i = blockIdx.x * blockDim.x + threadIdx.x;
    if (i >= NCODE * D_ / 16) return;
    const float4* p = (const float4*)in + 4 * (size_t)i;
    uint4 r;
    r.x = pack4(p[0]); r.y = pack4(p[1]); r.z = pack4(p[2]); r.w = pack4(p[3]);
    ((uint4*)g_cq)[i] = r;
}

// ---------------------------------------------------------------------------
// c2[n] = sum codes[n]^2 (exact fp32), +inf if inactive (uint8 or int32 bool).
__global__ void prep_c2_kernel(const float* __restrict__ codes,
                               const unsigned char* __restrict__ act8) {
    int n = blockIdx.x;
    const float* row = codes + (size_t)n * D_;
    float s = 0.f;
    for (int d = threadIdx.x; d < D_; d += 128) { float v = row[d]; s += v * v; }
    __shared__ float red[128];
    red[threadIdx.x] = s;
    __syncthreads();
    for (int off = 64; off; off >>= 1) {
        if (threadIdx.x < off) red[threadIdx.x] += red[threadIdx.x + off];
        __syncthreads();
    }
    if (threadIdx.x == 0) {
        bool int32mode = (act8[0] == 1) && (act8[1] == 0) && (act8[2] == 0) && (act8[3] == 0);
        bool a = int32mode ? (((const int*)act8)[n] != 0) : (act8[n] != 0);
        g_c2[n] = a ? red[0] : __int_as_float(0x7f800000);
    }
}

__global__ void prep_x2_kernel(const float* __restrict__ x) {
    int t = blockIdx.x;
    const float* row = x + (size_t)t * D_;
    float s = 0.f;
    for (int d = threadIdx.x; d < D_; d += 128) { float v = row[d]; s += v * v; }
    __shared__ float red[128];
    red[threadIdx.x] = s;
    __syncthreads();
    for (int off = 64; off; off >>= 1) {
        if (threadIdx.x < off) red[threadIdx.x] += red[threadIdx.x + off];
        __syncthreads();
    }
    if (threadIdx.x == 0) g_x2[t] = red[0];
}

// ---------------------------------------------------------------------------
__device__ __forceinline__ unsigned float_to_ordered(float f) {
    unsigned b = __float_as_uint(f);
    return (b & 0x80000000u) ? ~b : (b | 0x80000000u);
}

// ---------------------------------------------------------------------------
// Selection GEMM: int8 WMMA (16x16x16 s8 -> s32), 4 warps of 64x64 (2x2),
// BK=64, register double-buffered single-stage smem. Per-(split, col-quarter)
// winner per token; disjoint plain stores.
// ---------------------------------------------------------------------------
__global__ __launch_bounds__(128, 2) void gemm_s8_kernel() {
    __shared__ __align__(16) signed char sA[BM * SROWB];
    __shared__ __align__(16) signed char sB[BN * SROWB];
    __shared__ __align__(16) int sbuf[4][16 * 16];

    const int tid  = threadIdx.x;
    const int lane = tid & 31;
    const int warp = tid >> 5;      // 0..3
    const int wm = warp & 1;        // 0..1 -> 64 rows each
    const int wn = warp >> 1;       // 0..1 -> 64 cols each
    const int mBase  = blockIdx.x * BM;
    const int nChunk = blockIdx.y * NCHUNK;

    const int lrow = tid >> 2;           // 0..31 (rows +0,+32,+64,+96)
    const int lsegB = (tid & 3) * 16;    // byte offset 0,16,32,48 within the 64B row

    const signed char* Abase = g_xq + (size_t)(mBase + lrow) * D_ + lsegB;

    // running winners: [mi][col-quarter-within-warp(2)]
    float bestv[4][2];
    int   besti[4][2];
#pragma unroll
    for (int q = 0; q < 4; q++)
#pragma unroll
        for (int h = 0; h < 2; h++) { bestv[q][h] = __int_as_float(0x7f800000); besti[q][h] = nChunk; }

    for (int nt = 0; nt < NTILES; nt++) {
        const int nBase = nChunk + nt * BN;
        const signed char* Bbase = g_cq + (size_t)(nBase + lrow) * D_ + lsegB;

        wmma::fragment<wmma::accumulator, 16, 16, 16, int> acc[4][4];
#pragma unroll
        for (int mi = 0; mi < 4; mi++)
#pragma unroll
            for (int ni = 0; ni < 4; ni++) wmma::fill_fragment(acc[mi][ni], 0);

        // prologue: k-step 0 into registers
        uint4 rA[4], rB[4];
#pragma unroll
        for (int r = 0; r < 4; r++) {
            rA[r] = *(const uint4*)(Abase + (size_t)(r * 32) * D_);
            rB[r] = *(const uint4*)(Bbase + (size_t)(r * 32) * D_);
        }

        for (int kb = 0; kb < NKSTEP; kb++) {
            __syncthreads();   // previous k-step's MMAs done reading smem
#pragma unroll
            for (int r = 0; r < 4; r++) {
                *(uint4*)&sA[(lrow + r * 32) * SROWB + lsegB] = rA[r];
                *(uint4*)&sB[(lrow + r * 32) * SROWB + lsegB] = rB[r];
            }
            __syncthreads();
            if (kb + 1 < NKSTEP) {
                const int kg = (kb + 1) * BK;
#pragma unroll
                for (int r = 0; r < 4; r++) {
                    rA[r] = *(const uint4*)(Abase + (size_t)(r * 32) * D_ + kg);
                    rB[r] = *(const uint4*)(Bbase + (size_t)(r * 32) * D_ + kg);
                }
            }
#pragma unroll
            for (int ks = 0; ks < 4; ks++) {
                wmma::fragment<wmma::matrix_a, 16, 16, 16, signed char, wmma::row_major> fa[4];
#pragma unroll
                for (int mi = 0; mi < 4; mi++)
                    wmma::load_matrix_sync(fa[mi], &sA[(wm * 64 + mi * 16) * SROWB + ks * 16], SROWB);
#pragma unroll
                for (int ni = 0; ni < 4; ni++) {
                    // smem B is [n][k]; as a KxN matrix that's col_major with ldm=SROWB
                    wmma::fragment<wmma::matrix_b, 16, 16, 16, signed char, wmma::col_major> fb;
                    wmma::load_matrix_sync(fb, &sB[(wn * 64 + ni * 16) * SROWB + ks * 16], SROWB);
#pragma unroll
                    for (int mi = 0; mi < 4; mi++)
                        wmma::mma_sync(acc[mi][ni], fa[mi], fb, acc[mi][ni]);
                }
            }
        }

        // drain frags through smem (explicit indices), update running mins
#pragma unroll
        for (int mi = 0; mi < 4; mi++) {
#pragma unroll
            for (int ni = 0; ni < 4; ni++) {
                wmma::store_matrix_sync(&sbuf[warp][0], acc[mi][ni], 16, wmma::mem_row_major);
                __syncwarp();
                const int h = ni >> 1;       // col-quarter within this warp's half
                const int lr = lane >> 1;
                const int cb = (lane & 1) * 8;
                const int gcol0 = nBase + wn * 64 + ni * 16 + cb;
#pragma unroll
                for (int c = 0; c < 8; c++) {
                    int dot = sbuf[warp][lr * 16 + cb + c];
                    float s = fmaf(QNEG2, (float)dot, g_c2[gcol0 + c]);
                    if (s < bestv[mi][h]) { bestv[mi][h] = s; besti[mi][h] = gcol0 + c; }
                }
                __syncwarp();
            }
        }
    }

    // merge lane pairs and store per-(split, quarter) winner — disjoint slots.
#pragma unroll
    for (int mi = 0; mi < 4; mi++) {
#pragma unroll
        for (int h = 0; h < 2; h++) {
            unsigned long long key =
                (((unsigned long long)float_to_ordered(bestv[mi][h])) << 32) | (unsigned)besti[mi][h];
            unsigned long long o = __shfl_xor_sync(0xffffffffu, key, 1);
            if (o < key) key = o;
            if ((lane & 1) == 0) {
                int row = mBase + wm * 64 + mi * 16 + (lane >> 1);
                int slot = blockIdx.y * 4 + wn * 2 + h;
                g_cand[(size_t)row * NCAND + slot] = key;
            }
        }
    }
}

// ---------------------------------------------------------------------------
// Exact fp32 rescoring of the 64 nominees per token; emits final outputs.
// ---------------------------------------------------------------------------
__global__ __launch_bounds__(256) void refine_kernel(const float* __restrict__ x,
                                                     const float* __restrict__ codes,
                                                     float* __restrict__ out, int out_size) {
    const int t = blockIdx.x * 8 + (threadIdx.x >> 5);
    const int lane = threadIdx.x & 31;
    if (t >= MTOK) return;

    const float4* xr = (const float4*)(x + (size_t)t * D_);
    float4 xv[6];
#pragma unroll
    for (int j = 0; j < 6; j++) xv[j] = xr[lane + j * 32];

    unsigned long long best = 0xFFFFFFFFFFFFFFFFULL;

    for (int c = 0; c < NCAND; c++) {
        unsigned idx = (unsigned)(g_cand[(size_t)t * NCAND + c] & 0xffffffffu);
        if (idx >= NCODE) continue;             // safety guard
        const float4* cr = (const float4*)(codes + (size_t)idx * D_);
        float s = 0.f;
#pragma unroll
        for (int j = 0; j < 6; j++) {
            float4 cv = cr[lane + j * 32];
            s += xv[j].x * cv.x + xv[j].y * cv.y + xv[j].z * cv.z + xv[j].w * cv.w;
        }
#pragma unroll
        for (int off = 16; off; off >>= 1) s += __shfl_xor_sync(0xffffffffu, s, off);
        float dist = fmaf(-2.0f, s, g_c2[idx]);   // exact fp32 score; inf if inactive
        unsigned long long key =
            (((unsigned long long)float_to_ordered(dist)) << 32) | (unsigned long long)idx;
        if (key < best) best = key;
    }

    if (lane == 0) {
        unsigned u = (unsigned)(best >> 32);
        unsigned b = (u & 0x80000000u) ? (u & 0x7fffffffu) : ~u;
        float s = __uint_as_float(b);
        int idx = (int)(best & 0xffffffffu);
        float dmin = g_x2[t] + s;
        int idx_out = (dmin <= THRv) ? idx : -1;
        if (best == 0xFFFFFFFFFFFFFFFFULL) { idx_out = -1; dmin = __int_as_float(0x7f800000); }
        out[t] = (float)idx_out;
        if (out_size >= 2 * MTOK) out[MTOK + t] = dmin;
    }
}

// ---------------------------------------------------------------------------
extern "C" void kernel_launch(void* const* d_in, const int* in_sizes, int n_in,
                              void* d_out, int out_size) {
    const float* x     = (const float*)d_in[0];
    const float* codes = (const float*)d_in[1];
    const unsigned char* act = (const unsigned char*)d_in[2];

    cvt_x_kernel<<<(MTOK * D_ / 16 + 255) / 256, 256>>>(x);
    cvt_c_kernel<<<(NCODE * D_ / 16 + 255) / 256, 256>>>(codes);
    prep_c2_kernel<<<NCODE, 128>>>(codes, act);
    prep_x2_kernel<<<MTOK, 128>>>(x);
    gemm_s8_kernel<<<dim3(MTOK / BM, NSPLIT), 128>>>();
    refine_kernel<<<MTOK / 8, 256>>>(x, codes, (float*)d_out, out_size);
}